// round 1
// baseline (speedup 1.0000x reference)
#include <cuda_runtime.h>

// ---------------------------------------------------------------------------
// SynthesisLayer: StyleGAN2 modulated 3x3 conv, NHWC, N=16 H=W=64 C=O=512
// Round 1: correct fp32 baseline (direct conv, 9 shifted GEMMs, fused epilogue)
// ---------------------------------------------------------------------------

#define NN 16
#define HH 64
#define WW 64
#define CC 512
#define OO 512
#define NW 14

#define CK 8       // channel chunk per SMEM stage
#define TO 128     // output-channel tile per CTA
// spatial tile: 2 rows x 64 cols = 128 positions

// scratch (__device__ globals: allocation-free per harness rules)
__device__ float g_s[NN * CC];      // style per (n, c)
__device__ float g_dmul[NN * OO];   // wscale * demod  per (n, o)
__device__ float g_ssq[CC * OO];    // sum over 9 taps of weight^2, [i][o]

// ---- kernel 1: s[n,c] = dl[n,:] @ style_w / sqrt(512) + style_b ------------
__global__ void style_kernel(const float* __restrict__ dlat,
                             const float* __restrict__ sw,
                             const float* __restrict__ sb,
                             const int*   __restrict__ lidx)
{
    int n = blockIdx.x;
    int c = threadIdx.x;            // 512 threads
    __shared__ float dl[CC];
    int li = *lidx;
    dl[c] = dlat[(n * NW + li) * CC + c];
    __syncthreads();
    float acc = 0.f;
#pragma unroll 4
    for (int w = 0; w < CC; ++w)
        acc += dl[w] * sw[w * CC + c];
    g_s[n * CC + c] = acc * 0.044194173824159216f /* 1/sqrt(512) */ + sb[c];
}

// ---- kernel 2: ssq[i,o] = sum_tap weight[tap,i,o]^2 ------------------------
__global__ void ssq_kernel(const float* __restrict__ weight)
{
    int i = blockIdx.x;             // 512 blocks
    int o = threadIdx.x;            // 512 threads
    float acc = 0.f;
#pragma unroll
    for (int t = 0; t < 9; ++t) {
        float v = weight[(t * CC + i) * OO + o];
        acc += v * v;
    }
    g_ssq[i * OO + o] = acc;
}

// ---- kernel 3: dmul[n,o] = wscale * rsqrt(wscale^2 * sum_i s^2*ssq + 1e-8) -
__global__ void dmul_kernel()
{
    int n = blockIdx.x;             // 16 blocks
    int o = threadIdx.x;            // 512 threads
    __shared__ float s2[CC];
    float sv = g_s[n * CC + o];
    s2[o] = sv * sv;
    __syncthreads();
    float acc = 0.f;
#pragma unroll 4
    for (int i = 0; i < CC; ++i)
        acc += s2[i] * g_ssq[i * OO + o];
    const float ws2 = 1.0f / 4608.0f;                  // (1/sqrt(KKC))^2
    const float ws  = 0.014731391274719738f;           // 1/sqrt(4608)
    g_dmul[n * OO + o] = ws * rsqrtf(ws2 * acc + 1e-8f);
}

// ---- kernel 4: main conv, fused modulate/demod/noise/bias/lrelu ------------
// grid: (O tiles = 4, row tiles = 32, n = 16); block 256 threads.
// Thread (to = tid&15, ts = tid>>4): computes 8 spatial x 8 ochan outputs.
//   spatial: row = ts>>3 (0/1 within tile), cols = (ts&7)*8 .. +7 (contiguous)
//   ochan:   o = o0 + to*8 .. +7 (contiguous)
__global__ __launch_bounds__(256, 2)
void conv_kernel(const float* __restrict__ x,
                 const float* __restrict__ weight,
                 const float* __restrict__ bias,
                 const float* __restrict__ nstr,
                 const float* __restrict__ noise,
                 float* __restrict__ out)
{
    __shared__ float Xs[CK * 4 * 68];       // [c][4 rows][68 cols(pad)]  8.5 KB
    __shared__ float Ws[9 * CK * TO];       // [tap][c][128 o]           36.9 KB

    const int n  = blockIdx.z;
    const int r0 = blockIdx.y * 2;          // first output row of tile
    const int o0 = blockIdx.x * TO;         // first output channel of tile
    const int tid = threadIdx.x;
    const int to = tid & 15;
    const int ts = tid >> 4;
    const int row = ts >> 3;                // 0 or 1
    const int colbase = (ts & 7) * 8;       // 0..56

    float acc[8][8];
#pragma unroll
    for (int j = 0; j < 8; ++j)
#pragma unroll
        for (int oo = 0; oo < 8; ++oo) acc[j][oo] = 0.f;

    for (int c0 = 0; c0 < CC; c0 += CK) {
        // ---- stage X tile (4 rows x 66 cols x CK ch), s-modulated, zero-pad
        float sv[CK];
#pragma unroll
        for (int k = 0; k < CK; ++k) sv[k] = g_s[n * CC + c0 + k];

        int pi = tid;
#pragma unroll
        for (int it = 0; it < 2; ++it, pi += 256) {
            if (pi < 4 * 66) {
                int rr = pi / 66;           // smem row 0..3  (h = r0-1+rr)
                int sc = pi - rr * 66;      // smem col 0..65 (w = sc-1)
                int h = r0 - 1 + rr;
                int w = sc - 1;
                float4 v0 = make_float4(0.f, 0.f, 0.f, 0.f);
                float4 v1 = v0;
                if ((unsigned)h < HH && (unsigned)w < WW) {
                    const float* xp = x + (((n * HH + h) * WW + w) * CC + c0);
                    v0 = *(const float4*)xp;
                    v1 = *(const float4*)(xp + 4);
                }
                float vs[8] = {v0.x, v0.y, v0.z, v0.w, v1.x, v1.y, v1.z, v1.w};
#pragma unroll
                for (int k = 0; k < CK; ++k)
                    Xs[k * (4 * 68) + rr * 68 + sc] = vs[k] * sv[k];
            }
        }

        // ---- stage W tile: 9 taps x CK ch x 128 o  (2304 float4, 9/thread)
#pragma unroll
        for (int k = 0; k < 9; ++k) {
            int idx  = tid + k * 256;       // 0..2303
            int rowI = idx >> 5;            // (tap*CK + c), 0..71
            int cf   = idx & 31;            // float4 col
            int tap  = rowI >> 3;           // CK == 8
            int cc   = rowI & 7;
            const float4 v = *(const float4*)(weight +
                               ((tap * CC + c0 + cc) * OO + o0 + cf * 4));
            *(float4*)(&Ws[rowI * TO + cf * 4]) = v;
        }
        __syncthreads();

        // ---- compute: 9 taps x CK channels, 8x8 microtile
#pragma unroll 1
        for (int c = 0; c < CK; ++c) {
#pragma unroll
            for (int dy = 0; dy < 3; ++dy) {
                const float* xp = &Xs[(c * 4 + row + dy) * 68 + colbase];
                float av[10];
#pragma unroll
                for (int jj = 0; jj < 10; ++jj) av[jj] = xp[jj];
#pragma unroll
                for (int dx = 0; dx < 3; ++dx) {
                    const float* wp = &Ws[((dy * 3 + dx) * CK + c) * TO + to * 8];
                    float4 b0 = *(const float4*)wp;
                    float4 b1 = *(const float4*)(wp + 4);
                    float b[8] = {b0.x, b0.y, b0.z, b0.w, b1.x, b1.y, b1.z, b1.w};
#pragma unroll
                    for (int j = 0; j < 8; ++j)
#pragma unroll
                        for (int oo = 0; oo < 8; ++oo)
                            acc[j][oo] = fmaf(av[j + dx], b[oo], acc[j][oo]);
                }
            }
        }
        __syncthreads();
    }

    // ---- epilogue: demod, noise, bias, leaky_relu * sqrt(2)
    const float nstrv = *nstr;
    float dm[8], bi[8];
#pragma unroll
    for (int oo = 0; oo < 8; ++oo) {
        dm[oo] = g_dmul[n * OO + o0 + to * 8 + oo];
        bi[oo] = bias[o0 + to * 8 + oo];
    }
    const int outrow = r0 + row;
#pragma unroll
    for (int j = 0; j < 8; ++j) {
        int cw = colbase + j;
        float nz = noise[(n * HH + outrow) * WW + cw] * nstrv;
        float r[8];
#pragma unroll
        for (int oo = 0; oo < 8; ++oo) {
            float y = fmaf(acc[j][oo], dm[oo], nz + bi[oo]);
            y = (y > 0.f ? y : 0.2f * y) * 1.4142135623730951f;
            r[oo] = y;
        }
        int ob = ((n * HH + outrow) * WW + cw) * OO + o0 + to * 8;
        *(float4*)(out + ob)     = make_float4(r[0], r[1], r[2], r[3]);
        *(float4*)(out + ob + 4) = make_float4(r[4], r[5], r[6], r[7]);
    }
}

// ---------------------------------------------------------------------------
extern "C" void kernel_launch(void* const* d_in, const int* in_sizes, int n_in,
                              void* d_out, int out_size)
{
    const float* x      = (const float*)d_in[0];   // (16,64,64,512)
    const float* dlat   = (const float*)d_in[1];   // (16,14,512)
    const float* sw     = (const float*)d_in[2];   // (512,512)
    const float* sb     = (const float*)d_in[3];   // (512,)
    const float* weight = (const float*)d_in[4];   // (3,3,512,512)
    const float* bias   = (const float*)d_in[5];   // (512,)
    const float* nstr   = (const float*)d_in[6];   // scalar
    const float* noise  = (const float*)d_in[7];   // (16,64,64,1)
    const int*   lidx   = (const int*)  d_in[8];   // scalar int
    float* out = (float*)d_out;                    // (16,64,64,512)

    style_kernel<<<NN, CC>>>(dlat, sw, sb, lidx);
    ssq_kernel<<<CC, OO>>>(weight);
    dmul_kernel<<<NN, OO>>>();

    dim3 grid(OO / TO, HH / 2, NN);                // (4, 32, 16)
    conv_kernel<<<grid, 256>>>(x, weight, bias, nstr, noise, out);
}

// round 3
// speedup vs baseline: 2.1582x; 2.1582x over previous
#include <cuda_runtime.h>
#include <cuda_bf16.h>
#include <stdint.h>

// ---------------------------------------------------------------------------
// StyleGAN2 modulated 3x3 conv, NHWC, N=16 H=W=64 C=O=512
// Round 3: bf16 hi/lo 3-product implicit GEMM on mma.sync (base sm_103 ISA;
//          tcgen05 unavailable: harness PTX target lacks the 'a' suffix)
// ---------------------------------------------------------------------------

#define NN 16
#define HH 64
#define WW 64
#define CC 512
#define OO 512
#define NWD 14

#define STAGES 3
#define STAGE_BYTES 65536      // Ah 16K | Al 16K | Bh 16K | Bl 16K

// ---- device scratch (allocation-free) --------------------------------------
__device__ float g_s[NN * CC];
__device__ float g_dmul[NN * OO];
__device__ float g_ssq[CC * OO];
__device__ __nv_bfloat16 g_xh[NN * HH * WW * CC];   // modulated x, hi
__device__ __nv_bfloat16 g_xl[NN * HH * WW * CC];   // modulated x, lo
__device__ __nv_bfloat16 g_wh[9 * OO * CC];         // weight^T [tap][o][c], hi
__device__ __nv_bfloat16 g_wl[9 * OO * CC];         // weight^T [tap][o][c], lo

// ---- helpers -----------------------------------------------------------------
static __device__ __forceinline__ uint32_t smem_u32(const void* p) {
    uint32_t a;
    asm("{ .reg .u64 t; cvta.to.shared.u64 t, %1; cvt.u32.u64 %0, t; }"
        : "=r"(a) : "l"(p));
    return a;
}

#define CP16(dst, src, sz)                                                   \
    asm volatile("cp.async.cg.shared.global [%0], [%1], 16, %2;"             \
                 :: "r"(dst), "l"(src), "r"(sz) : "memory")
#define CP_COMMIT() asm volatile("cp.async.commit_group;" ::: "memory")
#define CP_WAIT1()  asm volatile("cp.async.wait_group 1;" ::: "memory")
#define CP_WAIT0()  asm volatile("cp.async.wait_group 0;" ::: "memory")

#define LDSM4(r, addr)                                                       \
    asm volatile("ldmatrix.sync.aligned.m8n8.x4.shared.b16 "                 \
                 "{%0,%1,%2,%3}, [%4];"                                      \
                 : "=r"((r)[0]), "=r"((r)[1]), "=r"((r)[2]), "=r"((r)[3])    \
                 : "r"(addr))

#define MMA(d, a, b)                                                         \
    asm volatile("mma.sync.aligned.m16n8k16.row.col.f32.bf16.bf16.f32 "      \
                 "{%0,%1,%2,%3}, {%4,%5,%6,%7}, {%8,%9}, {%0,%1,%2,%3};"     \
                 : "+f"((d)[0]), "+f"((d)[1]), "+f"((d)[2]), "+f"((d)[3])    \
                 : "r"((a)[0]), "r"((a)[1]), "r"((a)[2]), "r"((a)[3]),       \
                   "r"((b)[0]), "r"((b)[1]))

// ---- kernel 1: s[n,c] = dl @ style_w/sqrt(512) + style_b ----------------------
__global__ void style_kernel(const float* __restrict__ dlat,
                             const float* __restrict__ sw,
                             const float* __restrict__ sb,
                             const int*   __restrict__ lidx)
{
    int n = blockIdx.x;
    int c = threadIdx.x;
    __shared__ float dl[CC];
    int li = *lidx;
    dl[c] = dlat[(n * NWD + li) * CC + c];
    __syncthreads();
    float acc = 0.f;
#pragma unroll 4
    for (int w = 0; w < CC; ++w)
        acc += dl[w] * sw[w * CC + c];
    g_s[n * CC + c] = acc * 0.044194173824159216f + sb[c];
}

// ---- kernel 2: ssq[i,o] = sum_tap weight^2 ------------------------------------
__global__ void ssq_kernel(const float* __restrict__ weight)
{
    int i = blockIdx.x;
    int o = threadIdx.x;
    float acc = 0.f;
#pragma unroll
    for (int t = 0; t < 9; ++t) {
        float v = weight[(t * CC + i) * OO + o];
        acc += v * v;
    }
    g_ssq[i * OO + o] = acc;
}

// ---- kernel 3: dmul[n,o] -------------------------------------------------------
__global__ void dmul_kernel()
{
    int n = blockIdx.x;
    int o = threadIdx.x;
    __shared__ float s2[CC];
    float sv = g_s[n * CC + o];
    s2[o] = sv * sv;
    __syncthreads();
    float acc = 0.f;
#pragma unroll 4
    for (int i = 0; i < CC; ++i)
        acc += s2[i] * g_ssq[i * OO + o];
    const float ws2 = 1.0f / 4608.0f;
    const float ws  = 0.014731391274719738f;
    g_dmul[n * OO + o] = ws * rsqrtf(ws2 * acc + 1e-8f);
}

// ---- kernel 4: x*s -> bf16 hi/lo -----------------------------------------------
__global__ void xsplit_kernel(const float* __restrict__ x)
{
    int t = blockIdx.x * blockDim.x + threadIdx.x;
    int e = t * 4;
    int c = e & (CC - 1);
    int n = e >> 21;
    float4 v = *(const float4*)(x + e);
    float4 s = *(const float4*)(g_s + n * CC + c);
    float m0 = v.x * s.x, m1 = v.y * s.y, m2 = v.z * s.z, m3 = v.w * s.w;
    __nv_bfloat16 h0 = __float2bfloat16(m0), h1 = __float2bfloat16(m1);
    __nv_bfloat16 h2 = __float2bfloat16(m2), h3 = __float2bfloat16(m3);
    __nv_bfloat16 l0 = __float2bfloat16(m0 - __bfloat162float(h0));
    __nv_bfloat16 l1 = __float2bfloat16(m1 - __bfloat162float(h1));
    __nv_bfloat16 l2 = __float2bfloat16(m2 - __bfloat162float(h2));
    __nv_bfloat16 l3 = __float2bfloat16(m3 - __bfloat162float(h3));
    uint2 ph, pl;
    ph.x = (uint32_t)__bfloat16_as_ushort(h0) | ((uint32_t)__bfloat16_as_ushort(h1) << 16);
    ph.y = (uint32_t)__bfloat16_as_ushort(h2) | ((uint32_t)__bfloat16_as_ushort(h3) << 16);
    pl.x = (uint32_t)__bfloat16_as_ushort(l0) | ((uint32_t)__bfloat16_as_ushort(l1) << 16);
    pl.y = (uint32_t)__bfloat16_as_ushort(l2) | ((uint32_t)__bfloat16_as_ushort(l3) << 16);
    *(uint2*)(g_xh + e) = ph;
    *(uint2*)(g_xl + e) = pl;
}

// ---- kernel 5: weight transpose + bf16 hi/lo split ------------------------------
__global__ void wsplit_kernel(const float* __restrict__ weight)
{
    __shared__ float ts[32][33];
    int tap = blockIdx.z;
    int o0 = blockIdx.x * 32;
    int c0 = blockIdx.y * 32;
    int tx = threadIdx.x, ty = threadIdx.y;
    for (int j = ty; j < 32; j += 8)
        ts[j][tx] = weight[(tap * CC + c0 + j) * OO + o0 + tx];
    __syncthreads();
    for (int j = ty; j < 32; j += 8) {
        float v = ts[tx][j];
        __nv_bfloat16 h = __float2bfloat16(v);
        __nv_bfloat16 l = __float2bfloat16(v - __bfloat162float(h));
        int oi = (tap * OO + o0 + j) * CC + c0 + tx;
        g_wh[oi] = h;
        g_wl[oi] = l;
    }
}

// ---- chunk staging via cp.async (all 256 threads) -------------------------------
static __device__ __forceinline__ void load_chunk(uint32_t smbase, int stage, int ci,
                                                  int n, int h0, int o0, int tid)
{
    const int tap = ci >> 3;
    const int c0  = (ci & 7) * 64;
    const int dy  = tap / 3 - 1;
    const int dx  = tap % 3 - 1;
    const int r   = tid >> 1;                 // 0..127
    const int cb  = (tid & 1) * 4;            // 16B-chunk base within 128B row
    const int r7  = r & 7;
    const uint32_t sb = smbase + stage * STAGE_BYTES;

    // ---- A rows (spatial, tap-shifted, zero-filled halo)
    int hs = h0 + (r >> 6) + dy;
    int ws = (r & 63) + dx;
    const bool ok = ((unsigned)hs < (unsigned)HH) && ((unsigned)ws < (unsigned)WW);
    const unsigned szA = ok ? 16u : 0u;
    const int hc = ok ? hs : 0;
    const int wc = ok ? ws : 0;
    const size_t aidx = ((size_t)((n * HH + hc) * WW + wc) * CC + c0 + cb * 8) * 2;
    const char* srcAh = (const char*)g_xh + aidx;
    const char* srcAl = (const char*)g_xl + aidx;
#pragma unroll
    for (int c = 0; c < 4; ++c) {
        uint32_t d = sb + r * 128 + (((cb + c) ^ r7) << 4);
        CP16(d,          srcAh + c * 16, szA);
        CP16(d + 16384,  srcAl + c * 16, szA);
    }

    // ---- B rows (o channels; always in bounds)
    const size_t bidx = ((size_t)((tap * OO + o0 + r) * CC) + c0 + cb * 8) * 2;
    const char* srcBh = (const char*)g_wh + bidx;
    const char* srcBl = (const char*)g_wl + bidx;
#pragma unroll
    for (int c = 0; c < 4; ++c) {
        uint32_t d = sb + 32768 + r * 128 + (((cb + c) ^ r7) << 4);
        CP16(d,          srcBh + c * 16, 16u);
        CP16(d + 16384,  srcBl + c * 16, 16u);
    }
}

// ---- kernel 6: main conv on mma.sync ---------------------------------------------
__global__ __launch_bounds__(256, 1)
void conv_mma_kernel(const float* __restrict__ bias,
                     const float* __restrict__ nstr,
                     const float* __restrict__ noise,
                     float* __restrict__ out)
{
    extern __shared__ char dynsmem[];
    const uint32_t smbase = smem_u32(dynsmem);

    const int tid  = threadIdx.x;
    const int lane = tid & 31;
    const int wid  = tid >> 5;
    const int wm   = wid & 1;          // M half: 64 rows
    const int wn   = wid >> 1;         // N quarter: 32 cols

    const int o0 = blockIdx.x * 128;
    const int mt = blockIdx.y;         // 512 M tiles
    const int n  = mt >> 5;
    const int h0 = (mt & 31) * 2;      // 2 image rows per tile

    // ldmatrix per-lane row precompute
    const int a_row   = wm * 64 + (lane & 15);     // + mi*16
    const int a_khalf = lane >> 4;
    const int bg      = lane >> 3;
    const int b_row0  = wn * 32 + ((bg >> 1) << 3) + (lane & 7);  // + p*16
    const int b_khalf = bg & 1;

    float acc[4][4][4];
#pragma unroll
    for (int mi = 0; mi < 4; ++mi)
#pragma unroll
        for (int ni = 0; ni < 4; ++ni)
#pragma unroll
            for (int q = 0; q < 4; ++q) acc[mi][ni][q] = 0.f;

    // pipeline prologue
    load_chunk(smbase, 0, 0, n, h0, o0, tid); CP_COMMIT();
    load_chunk(smbase, 1, 1, n, h0, o0, tid); CP_COMMIT();

    int stage = 0;
    for (int i = 0; i < 72; ++i) {             // 9 taps x 8 c-chunks (kc=64)
        if (i < 71) CP_WAIT1(); else CP_WAIT0();
        __syncthreads();
        if (i + 2 < 72) {
            int ns = stage + 2; if (ns >= STAGES) ns -= STAGES;
            load_chunk(smbase, ns, i + 2, n, h0, o0, tid);
            CP_COMMIT();
        }

        const uint32_t sb = smbase + stage * STAGE_BYTES;
#pragma unroll
        for (int k16 = 0; k16 < 4; ++k16) {
            uint32_t ah[4][4], al[4][4], bh[4][2], bl[4][2];
#pragma unroll
            for (int mi = 0; mi < 4; ++mi) {
                int row = a_row + mi * 16;
                int ch  = 2 * k16 + a_khalf;
                uint32_t ad = sb + row * 128 + ((ch ^ (row & 7)) << 4);
                LDSM4(ah[mi], ad);
                LDSM4(al[mi], ad + 16384);
            }
#pragma unroll
            for (int p = 0; p < 2; ++p) {
                int row = b_row0 + p * 16;
                int ch  = 2 * k16 + b_khalf;
                uint32_t bd = sb + 32768 + row * 128 + ((ch ^ (row & 7)) << 4);
                uint32_t t0[4], t1[4];
                LDSM4(t0, bd);
                LDSM4(t1, bd + 16384);
                bh[p*2][0] = t0[0]; bh[p*2][1] = t0[1];
                bh[p*2+1][0] = t0[2]; bh[p*2+1][1] = t0[3];
                bl[p*2][0] = t1[0]; bl[p*2][1] = t1[1];
                bl[p*2+1][0] = t1[2]; bl[p*2+1][1] = t1[3];
            }
#pragma unroll
            for (int mi = 0; mi < 4; ++mi)
#pragma unroll
                for (int ni = 0; ni < 4; ++ni) {
                    MMA(acc[mi][ni], ah[mi], bh[ni]);
                    MMA(acc[mi][ni], ah[mi], bl[ni]);
                    MMA(acc[mi][ni], al[mi], bh[ni]);
                }
        }
        __syncthreads();
        ++stage; if (stage >= STAGES) stage = 0;
    }

    // ---- epilogue: demod, noise, bias, leaky_relu * sqrt(2)
    const float nstrv = *nstr;
#pragma unroll
    for (int mi = 0; mi < 4; ++mi) {
#pragma unroll
        for (int half = 0; half < 2; ++half) {
            int m = wm * 64 + mi * 16 + (lane >> 2) + half * 8;
            int h = h0 + (m >> 6);
            int w = m & 63;
            float nz = noise[(n * HH + h) * WW + w] * nstrv;
            size_t base = ((size_t)((n * HH + h) * WW + w)) * OO + o0;
#pragma unroll
            for (int ni = 0; ni < 4; ++ni) {
                int oc = wn * 32 + ni * 8 + 2 * (lane & 3);
                float dm0 = g_dmul[n * OO + o0 + oc];
                float dm1 = g_dmul[n * OO + o0 + oc + 1];
                float b0 = bias[o0 + oc], b1 = bias[o0 + oc + 1];
                float y0 = fmaf(acc[mi][ni][half * 2],     dm0, nz + b0);
                float y1 = fmaf(acc[mi][ni][half * 2 + 1], dm1, nz + b1);
                y0 = (y0 > 0.f ? y0 : 0.2f * y0) * 1.4142135623730951f;
                y1 = (y1 > 0.f ? y1 : 0.2f * y1) * 1.4142135623730951f;
                *(float2*)(out + base + oc) = make_float2(y0, y1);
            }
        }
    }
}

// ---------------------------------------------------------------------------
extern "C" void kernel_launch(void* const* d_in, const int* in_sizes, int n_in,
                              void* d_out, int out_size)
{
    const float* x      = (const float*)d_in[0];
    const float* dlat   = (const float*)d_in[1];
    const float* sw     = (const float*)d_in[2];
    const float* sbv    = (const float*)d_in[3];
    const float* weight = (const float*)d_in[4];
    const float* bias   = (const float*)d_in[5];
    const float* nstr   = (const float*)d_in[6];
    const float* noise  = (const float*)d_in[7];
    const int*   lidx   = (const int*)  d_in[8];
    float* out = (float*)d_out;

    style_kernel<<<NN, CC>>>(dlat, sw, sbv, lidx);
    ssq_kernel<<<CC, OO>>>(weight);
    dmul_kernel<<<NN, OO>>>();
    xsplit_kernel<<<32768, 256>>>(x);
    wsplit_kernel<<<dim3(16, 16, 9), dim3(32, 8)>>>(weight);

    const int smem_bytes = STAGES * STAGE_BYTES;   // 196608
    cudaFuncSetAttribute(conv_mma_kernel,
                         cudaFuncAttributeMaxDynamicSharedMemorySize, smem_bytes);
    conv_mma_kernel<<<dim3(4, 512), 256, smem_bytes>>>(bias, nstr, noise, out);
}

// round 4
// speedup vs baseline: 2.4001x; 1.1121x over previous
#include <cuda_runtime.h>
#include <cuda_bf16.h>
#include <stdint.h>

// ---------------------------------------------------------------------------
// StyleGAN2 modulated 3x3 conv, NHWC, N=16 H=W=64 C=O=512
// Round 4: mma.sync bf16 hi/lo 3-product, warp tile 64x64, CTA 128x256,
//          kc=64 two-stage cp.async pipeline. Pre-kernels fused (3 launches)
//          so the conv kernel lands in the ncu capture slot.
// ---------------------------------------------------------------------------

#define NN 16
#define HH 64
#define WW 64
#define CC 512
#define OO 512
#define NWD 14

#define STAGE_BYTES 98304   // Ah 16K | Al 16K | Bh 32K | Bl 32K
#define OFF_AL 16384
#define OFF_BH 32768
#define OFF_BL 65536

// ---- device scratch (allocation-free) --------------------------------------
__device__ float g_s[NN * CC];
__device__ float g_dmul[NN * OO];
__device__ float g_ssq[CC * OO];
__device__ __nv_bfloat16 g_xh[NN * HH * WW * CC];
__device__ __nv_bfloat16 g_xl[NN * HH * WW * CC];
__device__ __nv_bfloat16 g_wh[9 * OO * CC];        // [tap][o][c] hi
__device__ __nv_bfloat16 g_wl[9 * OO * CC];        // [tap][o][c] lo

// ---- helpers -----------------------------------------------------------------
static __device__ __forceinline__ uint32_t smem_u32(const void* p) {
    uint32_t a;
    asm("{ .reg .u64 t; cvta.to.shared.u64 t, %1; cvt.u32.u64 %0, t; }"
        : "=r"(a) : "l"(p));
    return a;
}

#define CP16(dst, src, sz)                                                   \
    asm volatile("cp.async.cg.shared.global [%0], [%1], 16, %2;"             \
                 :: "r"(dst), "l"(src), "r"(sz) : "memory")
#define CP_COMMIT() asm volatile("cp.async.commit_group;" ::: "memory")
#define CP_WAIT1()  asm volatile("cp.async.wait_group 1;" ::: "memory")
#define CP_WAIT0()  asm volatile("cp.async.wait_group 0;" ::: "memory")

#define LDSM4(r, addr)                                                       \
    asm volatile("ldmatrix.sync.aligned.m8n8.x4.shared.b16 "                 \
                 "{%0,%1,%2,%3}, [%4];"                                      \
                 : "=r"((r)[0]), "=r"((r)[1]), "=r"((r)[2]), "=r"((r)[3])    \
                 : "r"(addr))

#define MMA2(d, a, b0, b1)                                                   \
    asm volatile("mma.sync.aligned.m16n8k16.row.col.f32.bf16.bf16.f32 "      \
                 "{%0,%1,%2,%3}, {%4,%5,%6,%7}, {%8,%9}, {%0,%1,%2,%3};"     \
                 : "+f"((d)[0]), "+f"((d)[1]), "+f"((d)[2]), "+f"((d)[3])    \
                 : "r"((a)[0]), "r"((a)[1]), "r"((a)[2]), "r"((a)[3]),       \
                   "r"(b0), "r"(b1))

// ---- prep 1: style (blocks 0..15) + ssq (blocks 16..527) ----------------------
__global__ void prep1_kernel(const float* __restrict__ dlat,
                             const float* __restrict__ sw,
                             const float* __restrict__ sb,
                             const int*   __restrict__ lidx,
                             const float* __restrict__ weight)
{
    int bid = blockIdx.x;
    int t = threadIdx.x;
    if (bid < NN) {
        int n = bid;
        __shared__ float dl[CC];
        int li = *lidx;
        dl[t] = dlat[(n * NWD + li) * CC + t];
        __syncthreads();
        float acc = 0.f;
#pragma unroll 4
        for (int w = 0; w < CC; ++w)
            acc += dl[w] * sw[w * CC + t];
        g_s[n * CC + t] = acc * 0.044194173824159216f + sb[t];
    } else {
        int i = bid - NN;
        float acc = 0.f;
#pragma unroll
        for (int tp = 0; tp < 9; ++tp) {
            float v = weight[(tp * CC + i) * OO + t];
            acc += v * v;
        }
        g_ssq[i * OO + t] = acc;
    }
}

// ---- prep 2: dmul[n,o] ---------------------------------------------------------
__global__ void dmul_kernel()
{
    int n = blockIdx.x;
    int o = threadIdx.x;
    __shared__ float s2[CC];
    float sv = g_s[n * CC + o];
    s2[o] = sv * sv;
    __syncthreads();
    float acc = 0.f;
#pragma unroll 4
    for (int i = 0; i < CC; ++i)
        acc += s2[i] * g_ssq[i * OO + o];
    const float ws2 = 1.0f / 4608.0f;
    const float ws  = 0.014731391274719738f;
    g_dmul[n * OO + o] = ws * rsqrtf(ws2 * acc + 1e-8f);
}

// ---- prep 3: xsplit (blocks < 32768) + wsplit (rest) ----------------------------
__global__ void prep3_kernel(const float* __restrict__ x,
                             const float* __restrict__ weight)
{
    int bid = blockIdx.x;
    int tid = threadIdx.x;
    if (bid < 32768) {
        int t = bid * 256 + tid;
        int e = t * 4;
        int c = e & (CC - 1);
        int n = e >> 21;
        float4 v = *(const float4*)(x + e);
        float4 s = *(const float4*)(g_s + n * CC + c);
        float m0 = v.x * s.x, m1 = v.y * s.y, m2 = v.z * s.z, m3 = v.w * s.w;
        __nv_bfloat16 h0 = __float2bfloat16(m0), h1 = __float2bfloat16(m1);
        __nv_bfloat16 h2 = __float2bfloat16(m2), h3 = __float2bfloat16(m3);
        __nv_bfloat16 l0 = __float2bfloat16(m0 - __bfloat162float(h0));
        __nv_bfloat16 l1 = __float2bfloat16(m1 - __bfloat162float(h1));
        __nv_bfloat16 l2 = __float2bfloat16(m2 - __bfloat162float(h2));
        __nv_bfloat16 l3 = __float2bfloat16(m3 - __bfloat162float(h3));
        uint2 ph, pl;
        ph.x = (uint32_t)__bfloat16_as_ushort(h0) | ((uint32_t)__bfloat16_as_ushort(h1) << 16);
        ph.y = (uint32_t)__bfloat16_as_ushort(h2) | ((uint32_t)__bfloat16_as_ushort(h3) << 16);
        pl.x = (uint32_t)__bfloat16_as_ushort(l0) | ((uint32_t)__bfloat16_as_ushort(l1) << 16);
        pl.y = (uint32_t)__bfloat16_as_ushort(l2) | ((uint32_t)__bfloat16_as_ushort(l3) << 16);
        *(uint2*)(g_xh + e) = ph;
        *(uint2*)(g_xl + e) = pl;
    } else {
        __shared__ float ts[32][33];
        int wb = bid - 32768;            // 0..2303
        int tap = wb >> 8;
        int rem = wb & 255;
        int o0 = (rem & 15) * 32;
        int c0 = (rem >> 4) * 32;
        int tx = tid & 31, ty = tid >> 5;
        for (int j = ty; j < 32; j += 8)
            ts[j][tx] = weight[(tap * CC + c0 + j) * OO + o0 + tx];
        __syncthreads();
        for (int j = ty; j < 32; j += 8) {
            float v = ts[tx][j];
            __nv_bfloat16 h = __float2bfloat16(v);
            __nv_bfloat16 l = __float2bfloat16(v - __bfloat162float(h));
            int oi = (tap * OO + o0 + j) * CC + c0 + tx;
            g_wh[oi] = h;
            g_wl[oi] = l;
        }
    }
}

// ---- chunk staging via cp.async (256 threads) -----------------------------------
static __device__ __forceinline__ void load_chunk(uint32_t sb, int ci,
                                                  int n, int h0, int o0, int tid)
{
    const int tap = ci >> 3;
    const int c0  = (ci & 7) * 64;
    const int dy  = tap / 3 - 1;
    const int dx  = tap % 3 - 1;
    const int r   = tid >> 1;                 // 0..127
    const int cb  = (tid & 1) * 4;
    const int r7  = r & 7;

    // ---- A rows (128 spatial, tap-shifted, zero-filled halo)
    int hs = h0 + (r >> 6) + dy;
    int ws = (r & 63) + dx;
    const bool ok = ((unsigned)hs < (unsigned)HH) && ((unsigned)ws < (unsigned)WW);
    const unsigned szA = ok ? 16u : 0u;
    const int hc = ok ? hs : 0;
    const int wc = ok ? ws : 0;
    const size_t aidx = ((size_t)((n * HH + hc) * WW + wc) * CC + c0 + cb * 8) * 2;
    const char* srcAh = (const char*)g_xh + aidx;
    const char* srcAl = (const char*)g_xl + aidx;
#pragma unroll
    for (int c = 0; c < 4; ++c) {
        uint32_t d = sb + r * 128 + (((cb + c) ^ r7) << 4);
        CP16(d,          srcAh + c * 16, szA);
        CP16(d + OFF_AL, srcAl + c * 16, szA);
    }

    // ---- B rows (256 o-channels)
#pragma unroll
    for (int half = 0; half < 2; ++half) {
        const int rr = r + half * 128;
        const int rr7 = rr & 7;
        const size_t bidx = ((size_t)((tap * OO + o0 + rr) * CC) + c0 + cb * 8) * 2;
        const char* srcBh = (const char*)g_wh + bidx;
        const char* srcBl = (const char*)g_wl + bidx;
#pragma unroll
        for (int c = 0; c < 4; ++c) {
            uint32_t d = sb + rr * 128 + (((cb + c) ^ rr7) << 4);
            CP16(d + OFF_BH, srcBh + c * 16, 16u);
            CP16(d + OFF_BL, srcBl + c * 16, 16u);
        }
    }
}

// ---- kernel 4: main conv on mma.sync ---------------------------------------------
__global__ __launch_bounds__(256, 1)
void conv_mma_kernel(const float* __restrict__ bias,
                     const float* __restrict__ nstr,
                     const float* __restrict__ noise,
                     float* __restrict__ out)
{
    extern __shared__ char dynsmem[];
    const uint32_t smbase = smem_u32(dynsmem);

    const int tid  = threadIdx.x;
    const int lane = tid & 31;
    const int wid  = tid >> 5;
    const int wm   = wid & 1;          // M half (64 rows)
    const int wn   = wid >> 1;         // N quarter (64 cols)

    const int o0 = blockIdx.x * 256;
    const int mt = blockIdx.y;
    const int n  = mt >> 5;
    const int h0 = (mt & 31) * 2;

    // ldmatrix lane mappings
    const int a_row   = wm * 64 + (lane & 15);             // + mi*16
    const int a_kh    = lane >> 4;
    const int bg      = lane >> 3;
    const int b_row0  = wn * 64 + ((bg >> 1) << 3) + (lane & 7);   // + nb*16
    const int b_kh    = bg & 1;

    float acc[4][8][4];
#pragma unroll
    for (int mi = 0; mi < 4; ++mi)
#pragma unroll
        for (int ni = 0; ni < 8; ++ni)
#pragma unroll
            for (int q = 0; q < 4; ++q) acc[mi][ni][q] = 0.f;

    load_chunk(smbase, 0, n, h0, o0, tid);
    CP_COMMIT();

    for (int i = 0; i < 72; ++i) {             // 9 taps x 8 c-chunks (kc=64)
        if (i + 1 < 72) {
            load_chunk(smbase + ((i + 1) & 1) * STAGE_BYTES, i + 1, n, h0, o0, tid);
            CP_COMMIT();
            CP_WAIT1();
        } else {
            CP_WAIT0();
        }
        __syncthreads();

        const uint32_t sb = smbase + (i & 1) * STAGE_BYTES;
#pragma unroll
        for (int k16 = 0; k16 < 4; ++k16) {
            const int cha = 2 * k16 + a_kh;
            const int chb = 2 * k16 + b_kh;
            uint32_t ah[4][4], al[4][4], bb[4][4];
#pragma unroll
            for (int mi = 0; mi < 4; ++mi) {
                int row = a_row + mi * 16;
                uint32_t ad = sb + row * 128 + ((cha ^ (row & 7)) << 4);
                LDSM4(ah[mi], ad);
            }
#pragma unroll
            for (int nb = 0; nb < 4; ++nb) {
                int row = b_row0 + nb * 16;
                uint32_t bd = sb + OFF_BH + row * 128 + ((chb ^ (row & 7)) << 4);
                LDSM4(bb[nb], bd);
            }
            // hi x hi
#pragma unroll
            for (int mi = 0; mi < 4; ++mi)
#pragma unroll
                for (int nb = 0; nb < 4; ++nb) {
                    MMA2(acc[mi][2*nb],   ah[mi], bb[nb][0], bb[nb][1]);
                    MMA2(acc[mi][2*nb+1], ah[mi], bb[nb][2], bb[nb][3]);
                }
            // lo(A) x hi(B)
#pragma unroll
            for (int mi = 0; mi < 4; ++mi) {
                int row = a_row + mi * 16;
                uint32_t ad = sb + OFF_AL + row * 128 + ((cha ^ (row & 7)) << 4);
                LDSM4(al[mi], ad);
            }
#pragma unroll
            for (int mi = 0; mi < 4; ++mi)
#pragma unroll
                for (int nb = 0; nb < 4; ++nb) {
                    MMA2(acc[mi][2*nb],   al[mi], bb[nb][0], bb[nb][1]);
                    MMA2(acc[mi][2*nb+1], al[mi], bb[nb][2], bb[nb][3]);
                }
            // hi(A) x lo(B)
#pragma unroll
            for (int nb = 0; nb < 4; ++nb) {
                int row = b_row0 + nb * 16;
                uint32_t bd = sb + OFF_BL + row * 128 + ((chb ^ (row & 7)) << 4);
                LDSM4(bb[nb], bd);
            }
#pragma unroll
            for (int mi = 0; mi < 4; ++mi)
#pragma unroll
                for (int nb = 0; nb < 4; ++nb) {
                    MMA2(acc[mi][2*nb],   ah[mi], bb[nb][0], bb[nb][1]);
                    MMA2(acc[mi][2*nb+1], ah[mi], bb[nb][2], bb[nb][3]);
                }
        }
        __syncthreads();
    }

    // ---- epilogue: demod, noise, bias, leaky_relu * sqrt(2)
    const float nstrv = *nstr;
#pragma unroll
    for (int mi = 0; mi < 4; ++mi) {
#pragma unroll
        for (int half = 0; half < 2; ++half) {
            int m = wm * 64 + mi * 16 + (lane >> 2) + half * 8;
            int h = h0 + (m >> 6);
            int w = m & 63;
            float nz = noise[(n * HH + h) * WW + w] * nstrv;
            size_t base = ((size_t)((n * HH + h) * WW + w)) * OO + o0;
#pragma unroll
            for (int ni = 0; ni < 8; ++ni) {
                int oc = wn * 64 + ni * 8 + 2 * (lane & 3);
                float dm0 = g_dmul[n * OO + o0 + oc];
                float dm1 = g_dmul[n * OO + o0 + oc + 1];
                float b0 = bias[o0 + oc], b1 = bias[o0 + oc + 1];
                float y0 = fmaf(acc[mi][ni][half * 2],     dm0, nz + b0);
                float y1 = fmaf(acc[mi][ni][half * 2 + 1], dm1, nz + b1);
                y0 = (y0 > 0.f ? y0 : 0.2f * y0) * 1.4142135623730951f;
                y1 = (y1 > 0.f ? y1 : 0.2f * y1) * 1.4142135623730951f;
                *(float2*)(out + base + oc) = make_float2(y0, y1);
            }
        }
    }
}

// ---------------------------------------------------------------------------
extern "C" void kernel_launch(void* const* d_in, const int* in_sizes, int n_in,
                              void* d_out, int out_size)
{
    const float* x      = (const float*)d_in[0];
    const float* dlat   = (const float*)d_in[1];
    const float* sw     = (const float*)d_in[2];
    const float* sbv    = (const float*)d_in[3];
    const float* weight = (const float*)d_in[4];
    const float* bias   = (const float*)d_in[5];
    const float* nstr   = (const float*)d_in[6];
    const float* noise  = (const float*)d_in[7];
    const int*   lidx   = (const int*)  d_in[8];
    float* out = (float*)d_out;

    prep1_kernel<<<NN + CC, 512>>>(dlat, sw, sbv, lidx, weight);
    dmul_kernel<<<NN, 512>>>();
    prep3_kernel<<<32768 + 2304, 256>>>(x, weight);

    const int smem_bytes = 2 * STAGE_BYTES;   // 196608
    cudaFuncSetAttribute(conv_mma_kernel,
                         cudaFuncAttributeMaxDynamicSharedMemorySize, smem_bytes);
    conv_mma_kernel<<<dim3(2, 512), 256, smem_bytes>>>(bias, nstr, noise, out);
}

// round 5
// speedup vs baseline: 2.5132x; 1.0471x over previous
#include <cuda_runtime.h>
#include <cuda_bf16.h>
#include <stdint.h>

// ---------------------------------------------------------------------------
// StyleGAN2 modulated 3x3 conv, NHWC, N=16 H=W=64 C=O=512
// Round 5: mma.sync bf16 hi/lo 3-product. CTA 128x128, warp tile 32x64,
//          kc=32, double-buffered cp.async, ONE sync per chunk,
//          2 CTAs/SM (128 regs, 64KB smem) to cover barrier/load latency.
// ---------------------------------------------------------------------------

#define NN 16
#define HH 64
#define WW 64
#define CC 512
#define OO 512
#define NWD 14

#define STAGE_BYTES 32768   // Ah 8K | Al 8K | Bh 8K | Bl 8K
#define OFF_AL  8192
#define OFF_BH 16384
#define OFF_BL 24576
#define NCHUNK 144          // 9 taps x 16 c-chunks (kc=32)

// ---- device scratch (allocation-free) --------------------------------------
__device__ float g_s[NN * CC];
__device__ float g_dmul[NN * OO];
__device__ float g_ssq[CC * OO];
__device__ __nv_bfloat16 g_xh[NN * HH * WW * CC];
__device__ __nv_bfloat16 g_xl[NN * HH * WW * CC];
__device__ __nv_bfloat16 g_wh[9 * OO * CC];        // [tap][o][c] hi
__device__ __nv_bfloat16 g_wl[9 * OO * CC];        // [tap][o][c] lo

// ---- helpers -----------------------------------------------------------------
static __device__ __forceinline__ uint32_t smem_u32(const void* p) {
    uint32_t a;
    asm("{ .reg .u64 t; cvta.to.shared.u64 t, %1; cvt.u32.u64 %0, t; }"
        : "=r"(a) : "l"(p));
    return a;
}

#define CP16(dst, src, sz)                                                   \
    asm volatile("cp.async.cg.shared.global [%0], [%1], 16, %2;"             \
                 :: "r"(dst), "l"(src), "r"(sz) : "memory")
#define CP_COMMIT() asm volatile("cp.async.commit_group;" ::: "memory")
#define CP_WAIT0()  asm volatile("cp.async.wait_group 0;" ::: "memory")

#define LDSM4(r, addr)                                                       \
    asm volatile("ldmatrix.sync.aligned.m8n8.x4.shared.b16 "                 \
                 "{%0,%1,%2,%3}, [%4];"                                      \
                 : "=r"((r)[0]), "=r"((r)[1]), "=r"((r)[2]), "=r"((r)[3])    \
                 : "r"(addr))

#define MMA2(d, a, b0, b1)                                                   \
    asm volatile("mma.sync.aligned.m16n8k16.row.col.f32.bf16.bf16.f32 "      \
                 "{%0,%1,%2,%3}, {%4,%5,%6,%7}, {%8,%9}, {%0,%1,%2,%3};"     \
                 : "+f"((d)[0]), "+f"((d)[1]), "+f"((d)[2]), "+f"((d)[3])    \
                 : "r"((a)[0]), "r"((a)[1]), "r"((a)[2]), "r"((a)[3]),       \
                   "r"(b0), "r"(b1))

// 64B rows, 4x16B chunks, swizzle chunk ^= (row>>1)&3  (conflict-free for
// 8-row ldmatrix phases: evens/odds each hit 4 distinct 16B banksets)
#define SWZ(row, chunk) (((row) * 64) + ((((chunk) ^ (((row) >> 1) & 3))) << 4))

// ---- prep 1: style (blocks 0..15) + ssq (blocks 16..527) ----------------------
__global__ void prep1_kernel(const float* __restrict__ dlat,
                             const float* __restrict__ sw,
                             const float* __restrict__ sb,
                             const int*   __restrict__ lidx,
                             const float* __restrict__ weight)
{
    int bid = blockIdx.x;
    int t = threadIdx.x;
    if (bid < NN) {
        int n = bid;
        __shared__ float dl[CC];
        int li = *lidx;
        dl[t] = dlat[(n * NWD + li) * CC + t];
        __syncthreads();
        float acc = 0.f;
#pragma unroll 4
        for (int w = 0; w < CC; ++w)
            acc += dl[w] * sw[w * CC + t];
        g_s[n * CC + t] = acc * 0.044194173824159216f + sb[t];
    } else {
        int i = bid - NN;
        float acc = 0.f;
#pragma unroll
        for (int tp = 0; tp < 9; ++tp) {
            float v = weight[(tp * CC + i) * OO + t];
            acc += v * v;
        }
        g_ssq[i * OO + t] = acc;
    }
}

// ---- prep 2: dmul[n,o] ---------------------------------------------------------
__global__ void dmul_kernel()
{
    int n = blockIdx.x;
    int o = threadIdx.x;
    __shared__ float s2[CC];
    float sv = g_s[n * CC + o];
    s2[o] = sv * sv;
    __syncthreads();
    float acc = 0.f;
#pragma unroll 4
    for (int i = 0; i < CC; ++i)
        acc += s2[i] * g_ssq[i * OO + o];
    const float ws2 = 1.0f / 4608.0f;
    const float ws  = 0.014731391274719738f;
    g_dmul[n * OO + o] = ws * rsqrtf(ws2 * acc + 1e-8f);
}

// ---- prep 3: xsplit (blocks < 32768) + wsplit (rest) ----------------------------
__global__ void prep3_kernel(const float* __restrict__ x,
                             const float* __restrict__ weight)
{
    int bid = blockIdx.x;
    int tid = threadIdx.x;
    if (bid < 32768) {
        int t = bid * 256 + tid;
        int e = t * 4;
        int c = e & (CC - 1);
        int n = e >> 21;
        float4 v = *(const float4*)(x + e);
        float4 s = *(const float4*)(g_s + n * CC + c);
        float m0 = v.x * s.x, m1 = v.y * s.y, m2 = v.z * s.z, m3 = v.w * s.w;
        __nv_bfloat16 h0 = __float2bfloat16(m0), h1 = __float2bfloat16(m1);
        __nv_bfloat16 h2 = __float2bfloat16(m2), h3 = __float2bfloat16(m3);
        __nv_bfloat16 l0 = __float2bfloat16(m0 - __bfloat162float(h0));
        __nv_bfloat16 l1 = __float2bfloat16(m1 - __bfloat162float(h1));
        __nv_bfloat16 l2 = __float2bfloat16(m2 - __bfloat162float(h2));
        __nv_bfloat16 l3 = __float2bfloat16(m3 - __bfloat162float(h3));
        uint2 ph, pl;
        ph.x = (uint32_t)__bfloat16_as_ushort(h0) | ((uint32_t)__bfloat16_as_ushort(h1) << 16);
        ph.y = (uint32_t)__bfloat16_as_ushort(h2) | ((uint32_t)__bfloat16_as_ushort(h3) << 16);
        pl.x = (uint32_t)__bfloat16_as_ushort(l0) | ((uint32_t)__bfloat16_as_ushort(l1) << 16);
        pl.y = (uint32_t)__bfloat16_as_ushort(l2) | ((uint32_t)__bfloat16_as_ushort(l3) << 16);
        *(uint2*)(g_xh + e) = ph;
        *(uint2*)(g_xl + e) = pl;
    } else {
        __shared__ float ts[32][33];
        int wb = bid - 32768;            // 0..2303
        int tap = wb >> 8;
        int rem = wb & 255;
        int o0 = (rem & 15) * 32;
        int c0 = (rem >> 4) * 32;
        int tx = tid & 31, ty = tid >> 5;
        for (int j = ty; j < 32; j += 8)
            ts[j][tx] = weight[(tap * CC + c0 + j) * OO + o0 + tx];
        __syncthreads();
        for (int j = ty; j < 32; j += 8) {
            float v = ts[tx][j];
            __nv_bfloat16 h = __float2bfloat16(v);
            __nv_bfloat16 l = __float2bfloat16(v - __bfloat162float(h));
            int oi = (tap * OO + o0 + j) * CC + c0 + tx;
            g_wh[oi] = h;
            g_wl[oi] = l;
        }
    }
}

// ---- chunk staging via cp.async (256 threads, 8x16B each) -----------------------
static __device__ __forceinline__ void load_chunk(uint32_t sb, int ci,
                                                  int n, int h0, int o0, int tid)
{
    const int tap = ci >> 4;              // 0..8
    const int c0  = (ci & 15) * 32;       // kc=32
    const int dy  = tap / 3 - 1;
    const int dx  = tap % 3 - 1;
    const int r   = tid >> 1;             // 0..127
    const int cb  = (tid & 1) * 2;        // chunk base (2 chunks of 16B)
    const int sw  = (r >> 1) & 3;

    // ---- A rows (128 spatial, tap-shifted, zero-filled halo)
    int hs = h0 + (r >> 6) + dy;
    int ws = (r & 63) + dx;
    const bool ok = ((unsigned)hs < (unsigned)HH) && ((unsigned)ws < (unsigned)WW);
    const unsigned szA = ok ? 16u : 0u;
    const int hc = ok ? hs : 0;
    const int wc = ok ? ws : 0;
    const size_t aidx = ((size_t)((n * HH + hc) * WW + wc) * CC + c0 + cb * 8) * 2;
    const char* srcAh = (const char*)g_xh + aidx;
    const char* srcAl = (const char*)g_xl + aidx;
#pragma unroll
    for (int c = 0; c < 2; ++c) {
        uint32_t d = sb + r * 64 + (((cb + c) ^ sw) << 4);
        CP16(d,          srcAh + c * 16, szA);
        CP16(d + OFF_AL, srcAl + c * 16, szA);
    }

    // ---- B rows (128 o-channels)
    const size_t bidx = ((size_t)((tap * OO + o0 + r) * CC) + c0 + cb * 8) * 2;
    const char* srcBh = (const char*)g_wh + bidx;
    const char* srcBl = (const char*)g_wl + bidx;
#pragma unroll
    for (int c = 0; c < 2; ++c) {
        uint32_t d = sb + r * 64 + (((cb + c) ^ sw) << 4);
        CP16(d + OFF_BH, srcBh + c * 16, 16u);
        CP16(d + OFF_BL, srcBl + c * 16, 16u);
    }
}

// ---- kernel 4: main conv on mma.sync ---------------------------------------------
__global__ __launch_bounds__(256, 2)
void conv_mma_kernel(const float* __restrict__ bias,
                     const float* __restrict__ nstr,
                     const float* __restrict__ noise,
                     float* __restrict__ out)
{
    extern __shared__ char dynsmem[];
    const uint32_t smbase = smem_u32(dynsmem);

    const int tid  = threadIdx.x;
    const int lane = tid & 31;
    const int wid  = tid >> 5;
    const int wm   = wid & 3;          // M quarter (32 rows)
    const int wn   = wid >> 2;         // N half (64 cols)

    const int o0 = blockIdx.x * 128;
    const int mt = blockIdx.y;
    const int n  = mt >> 5;
    const int h0 = (mt & 31) * 2;

    // ldmatrix lane mappings
    const int a_row  = wm * 32 + (lane & 15);            // + mi*16
    const int a_kh   = lane >> 4;                        // k-half
    const int bg     = lane >> 3;
    const int b_row0 = wn * 64 + ((bg >> 1) << 3) + (lane & 7);  // + nb*16
    const int b_kh   = bg & 1;

    float acc[2][8][4];
#pragma unroll
    for (int mi = 0; mi < 2; ++mi)
#pragma unroll
        for (int ni = 0; ni < 8; ++ni)
#pragma unroll
            for (int q = 0; q < 4; ++q) acc[mi][ni][q] = 0.f;

    load_chunk(smbase, 0, n, h0, o0, tid);
    CP_COMMIT();

    for (int i = 0; i < NCHUNK; ++i) {
        CP_WAIT0();              // chunk i resident (this thread's copies)
        __syncthreads();         // all copies visible; all warps done with i-1
        if (i + 1 < NCHUNK) {    // prefetch i+1 into the buffer i-1 used
            load_chunk(smbase + ((i + 1) & 1) * STAGE_BYTES, i + 1, n, h0, o0, tid);
            CP_COMMIT();
        }

        const uint32_t sb = smbase + (i & 1) * STAGE_BYTES;
#pragma unroll
        for (int kk = 0; kk < 2; ++kk) {
            const int cha = kk * 2 + a_kh;
            const int chb = kk * 2 + b_kh;
            uint32_t ah[2][4], al[2][4], bb[4][4];
#pragma unroll
            for (int mi = 0; mi < 2; ++mi) {
                int row = a_row + mi * 16;
                LDSM4(ah[mi], sb + SWZ(row, cha));
            }
#pragma unroll
            for (int nb = 0; nb < 4; ++nb) {
                int row = b_row0 + nb * 16;
                LDSM4(bb[nb], sb + OFF_BH + SWZ(row, chb));
            }
            // hi x hi
#pragma unroll
            for (int mi = 0; mi < 2; ++mi)
#pragma unroll
                for (int nb = 0; nb < 4; ++nb) {
                    MMA2(acc[mi][2*nb],   ah[mi], bb[nb][0], bb[nb][1]);
                    MMA2(acc[mi][2*nb+1], ah[mi], bb[nb][2], bb[nb][3]);
                }
            // lo(A) x hi(B)
#pragma unroll
            for (int mi = 0; mi < 2; ++mi) {
                int row = a_row + mi * 16;
                LDSM4(al[mi], sb + OFF_AL + SWZ(row, cha));
            }
#pragma unroll
            for (int mi = 0; mi < 2; ++mi)
#pragma unroll
                for (int nb = 0; nb < 4; ++nb) {
                    MMA2(acc[mi][2*nb],   al[mi], bb[nb][0], bb[nb][1]);
                    MMA2(acc[mi][2*nb+1], al[mi], bb[nb][2], bb[nb][3]);
                }
            // hi(A) x lo(B)
#pragma unroll
            for (int nb = 0; nb < 4; ++nb) {
                int row = b_row0 + nb * 16;
                LDSM4(bb[nb], sb + OFF_BL + SWZ(row, chb));
            }
#pragma unroll
            for (int mi = 0; mi < 2; ++mi)
#pragma unroll
                for (int nb = 0; nb < 4; ++nb) {
                    MMA2(acc[mi][2*nb],   ah[mi], bb[nb][0], bb[nb][1]);
                    MMA2(acc[mi][2*nb+1], ah[mi], bb[nb][2], bb[nb][3]);
                }
        }
    }

    // ---- epilogue: demod, noise, bias, leaky_relu * sqrt(2)
    const float nstrv = *nstr;
#pragma unroll
    for (int mi = 0; mi < 2; ++mi) {
#pragma unroll
        for (int half = 0; half < 2; ++half) {
            int m = wm * 32 + mi * 16 + (lane >> 2) + half * 8;
            int h = h0 + (m >> 6);
            int w = m & 63;
            float nz = noise[(n * HH + h) * WW + w] * nstrv;
            size_t base = ((size_t)((n * HH + h) * WW + w)) * OO + o0;
#pragma unroll
            for (int ni = 0; ni < 8; ++ni) {
                int oc = wn * 64 + ni * 8 + 2 * (lane & 3);
                float dm0 = g_dmul[n * OO + o0 + oc];
                float dm1 = g_dmul[n * OO + o0 + oc + 1];
                float b0 = bias[o0 + oc], b1 = bias[o0 + oc + 1];
                float y0 = fmaf(acc[mi][ni][half * 2],     dm0, nz + b0);
                float y1 = fmaf(acc[mi][ni][half * 2 + 1], dm1, nz + b1);
                y0 = (y0 > 0.f ? y0 : 0.2f * y0) * 1.4142135623730951f;
                y1 = (y1 > 0.f ? y1 : 0.2f * y1) * 1.4142135623730951f;
                *(float2*)(out + base + oc) = make_float2(y0, y1);
            }
        }
    }
}

// ---------------------------------------------------------------------------
extern "C" void kernel_launch(void* const* d_in, const int* in_sizes, int n_in,
                              void* d_out, int out_size)
{
    const float* x      = (const float*)d_in[0];
    const float* dlat   = (const float*)d_in[1];
    const float* sw     = (const float*)d_in[2];
    const float* sbv    = (const float*)d_in[3];
    const float* weight = (const float*)d_in[4];
    const float* bias   = (const float*)d_in[5];
    const float* nstr   = (const float*)d_in[6];
    const float* noise  = (const float*)d_in[7];
    const int*   lidx   = (const int*)  d_in[8];
    float* out = (float*)d_out;

    prep1_kernel<<<NN + CC, 512>>>(dlat, sw, sbv, lidx, weight);
    dmul_kernel<<<NN, 512>>>();
    prep3_kernel<<<32768 + 2304, 256>>>(x, weight);

    const int smem_bytes = 2 * STAGE_BYTES;   // 65536 per CTA
    cudaFuncSetAttribute(conv_mma_kernel,
                         cudaFuncAttributeMaxDynamicSharedMemorySize, smem_bytes);
    conv_mma_kernel<<<dim3(4, 512), 256, smem_bytes>>>(bias, nstr, noise, out);
}

// round 6
// speedup vs baseline: 3.4761x; 1.3831x over previous
#include <cuda_runtime.h>
#include <cuda_fp16.h>
#include <cuda_bf16.h>
#include <stdint.h>

// ---------------------------------------------------------------------------
// StyleGAN2 modulated 3x3 conv, NHWC, N=16 H=W=64 C=O=512
// Round 6: fp16 2-product split on mma.sync:  y = xh*w + xl*w
//          (x*s split hi/lo fp16; w single fp16 -> only error = w rounding,
//           predicted rel_err ~2e-4). Tensor work cut 33% vs round 5.
//          CTA 128x128, warp 32x64, kc=64, double buffer, 2 CTAs/SM.
// ---------------------------------------------------------------------------

#define NN 16
#define HH 64
#define WW 64
#define CC 512
#define OO 512
#define NWD 14

#define STAGE_BYTES 49152   // Ah 16K | Al 16K | B 16K
#define OFF_AL 16384
#define OFF_B  32768
#define NCHUNK 72           // 9 taps x 8 c-chunks (kc=64)

// ---- device scratch (allocation-free) --------------------------------------
__device__ float g_s[NN * CC];
__device__ float g_dmul[NN * OO];
__device__ float g_ssq[CC * OO];
__device__ __half g_xh[NN * HH * WW * CC];   // fp16 hi of x*s
__device__ __half g_xl[NN * HH * WW * CC];   // fp16 lo of x*s
__device__ __half g_wt[9 * OO * CC];         // fp16 w^T [tap][o][c]

// ---- helpers -----------------------------------------------------------------
static __device__ __forceinline__ uint32_t smem_u32(const void* p) {
    uint32_t a;
    asm("{ .reg .u64 t; cvta.to.shared.u64 t, %1; cvt.u32.u64 %0, t; }"
        : "=r"(a) : "l"(p));
    return a;
}

#define CP16(dst, src, sz)                                                   \
    asm volatile("cp.async.cg.shared.global [%0], [%1], 16, %2;"             \
                 :: "r"(dst), "l"(src), "r"(sz) : "memory")
#define CP_COMMIT() asm volatile("cp.async.commit_group;" ::: "memory")
#define CP_WAIT0()  asm volatile("cp.async.wait_group 0;" ::: "memory")

#define LDSM4(r, addr)                                                       \
    asm volatile("ldmatrix.sync.aligned.m8n8.x4.shared.b16 "                 \
                 "{%0,%1,%2,%3}, [%4];"                                      \
                 : "=r"((r)[0]), "=r"((r)[1]), "=r"((r)[2]), "=r"((r)[3])    \
                 : "r"(addr))

#define MMA2(d, a, b0, b1)                                                   \
    asm volatile("mma.sync.aligned.m16n8k16.row.col.f32.f16.f16.f32 "        \
                 "{%0,%1,%2,%3}, {%4,%5,%6,%7}, {%8,%9}, {%0,%1,%2,%3};"     \
                 : "+f"((d)[0]), "+f"((d)[1]), "+f"((d)[2]), "+f"((d)[3])    \
                 : "r"((a)[0]), "r"((a)[1]), "r"((a)[2]), "r"((a)[3]),       \
                   "r"(b0), "r"(b1))

// 128B rows, 8x16B chunks, XOR swizzle by row&7 (conflict-free ldmatrix)
#define SWZ128(row, ch) (((row) * 128) + ((((ch) ^ ((row) & 7))) << 4))

// ---- prep 1: style (blocks 0..15) + ssq (blocks 16..527) ----------------------
__global__ void prep1_kernel(const float* __restrict__ dlat,
                             const float* __restrict__ sw,
                             const float* __restrict__ sb,
                             const int*   __restrict__ lidx,
                             const float* __restrict__ weight)
{
    int bid = blockIdx.x;
    int t = threadIdx.x;
    if (bid < NN) {
        int n = bid;
        __shared__ float dl[CC];
        int li = *lidx;
        dl[t] = dlat[(n * NWD + li) * CC + t];
        __syncthreads();
        float acc = 0.f;
#pragma unroll 4
        for (int w = 0; w < CC; ++w)
            acc += dl[w] * sw[w * CC + t];
        g_s[n * CC + t] = acc * 0.044194173824159216f + sb[t];
    } else {
        int i = bid - NN;
        float acc = 0.f;
#pragma unroll
        for (int tp = 0; tp < 9; ++tp) {
            float v = weight[(tp * CC + i) * OO + t];
            acc += v * v;
        }
        g_ssq[i * OO + t] = acc;
    }
}

// ---- prep 2: dmul[n,o] ---------------------------------------------------------
__global__ void dmul_kernel()
{
    int n = blockIdx.x;
    int o = threadIdx.x;
    __shared__ float s2[CC];
    float sv = g_s[n * CC + o];
    s2[o] = sv * sv;
    __syncthreads();
    float acc = 0.f;
#pragma unroll 4
    for (int i = 0; i < CC; ++i)
        acc += s2[i] * g_ssq[i * OO + o];
    const float ws2 = 1.0f / 4608.0f;
    const float ws  = 0.014731391274719738f;
    g_dmul[n * OO + o] = ws * rsqrtf(ws2 * acc + 1e-8f);
}

// ---- prep 3: xsplit fp16 (blocks < 32768) + w transpose fp16 (rest) -------------
__global__ void prep3_kernel(const float* __restrict__ x,
                             const float* __restrict__ weight)
{
    int bid = blockIdx.x;
    int tid = threadIdx.x;
    if (bid < 32768) {
        int t = bid * 256 + tid;
        int e = t * 4;
        int c = e & (CC - 1);
        int n = e >> 21;
        float4 v = *(const float4*)(x + e);
        float4 s = *(const float4*)(g_s + n * CC + c);
        float m0 = v.x * s.x, m1 = v.y * s.y, m2 = v.z * s.z, m3 = v.w * s.w;
        __half h0 = __float2half_rn(m0), h1 = __float2half_rn(m1);
        __half h2 = __float2half_rn(m2), h3 = __float2half_rn(m3);
        __half l0 = __float2half_rn(m0 - __half2float(h0));
        __half l1 = __float2half_rn(m1 - __half2float(h1));
        __half l2 = __float2half_rn(m2 - __half2float(h2));
        __half l3 = __float2half_rn(m3 - __half2float(h3));
        uint2 ph, pl;
        ph.x = (uint32_t)__half_as_ushort(h0) | ((uint32_t)__half_as_ushort(h1) << 16);
        ph.y = (uint32_t)__half_as_ushort(h2) | ((uint32_t)__half_as_ushort(h3) << 16);
        pl.x = (uint32_t)__half_as_ushort(l0) | ((uint32_t)__half_as_ushort(l1) << 16);
        pl.y = (uint32_t)__half_as_ushort(l2) | ((uint32_t)__half_as_ushort(l3) << 16);
        *(uint2*)(g_xh + e) = ph;
        *(uint2*)(g_xl + e) = pl;
    } else {
        __shared__ float ts[32][33];
        int wb = bid - 32768;            // 0..2303
        int tap = wb >> 8;
        int rem = wb & 255;
        int o0 = (rem & 15) * 32;
        int c0 = (rem >> 4) * 32;
        int tx = tid & 31, ty = tid >> 5;
        for (int j = ty; j < 32; j += 8)
            ts[j][tx] = weight[(tap * CC + c0 + j) * OO + o0 + tx];
        __syncthreads();
        for (int j = ty; j < 32; j += 8) {
            float v = ts[tx][j];
            int oi = (tap * OO + o0 + j) * CC + c0 + tx;
            g_wt[oi] = __float2half_rn(v);
        }
    }
}

// ---- chunk staging via cp.async (256 threads, 12x16B each) ----------------------
static __device__ __forceinline__ void load_chunk(uint32_t sb, int ci,
                                                  int n, int h0, int o0, int tid)
{
    const int tap = ci >> 3;              // 0..8
    const int c0  = (ci & 7) * 64;        // kc=64
    const int dy  = tap / 3 - 1;
    const int dx  = tap % 3 - 1;
    const int r   = tid >> 1;             // 0..127
    const int cb  = (tid & 1) * 4;        // 4 consecutive 16B chunks
    const int r7  = r & 7;

    // ---- A rows (128 spatial, tap-shifted, zero-filled halo), hi + lo
    int hs = h0 + (r >> 6) + dy;
    int ws = (r & 63) + dx;
    const bool ok = ((unsigned)hs < (unsigned)HH) && ((unsigned)ws < (unsigned)WW);
    const unsigned szA = ok ? 16u : 0u;
    const int hc = ok ? hs : 0;
    const int wc = ok ? ws : 0;
    const size_t aidx = ((size_t)((n * HH + hc) * WW + wc) * CC + c0 + cb * 8) * 2;
    const char* srcAh = (const char*)g_xh + aidx;
    const char* srcAl = (const char*)g_xl + aidx;
#pragma unroll
    for (int c = 0; c < 4; ++c) {
        uint32_t d = sb + r * 128 + (((cb + c) ^ r7) << 4);
        CP16(d,          srcAh + c * 16, szA);
        CP16(d + OFF_AL, srcAl + c * 16, szA);
    }

    // ---- B rows (128 o-channels, single fp16)
    const size_t bidx = ((size_t)((tap * OO + o0 + r) * CC) + c0 + cb * 8) * 2;
    const char* srcB = (const char*)g_wt + bidx;
#pragma unroll
    for (int c = 0; c < 4; ++c) {
        uint32_t d = sb + OFF_B + r * 128 + (((cb + c) ^ r7) << 4);
        CP16(d, srcB + c * 16, 16u);
    }
}

// ---- kernel 4: main conv on mma.sync ---------------------------------------------
__global__ __launch_bounds__(256, 2)
void conv_mma_kernel(const float* __restrict__ bias,
                     const float* __restrict__ nstr,
                     const float* __restrict__ noise,
                     float* __restrict__ out)
{
    extern __shared__ char dynsmem[];
    const uint32_t smbase = smem_u32(dynsmem);

    const int tid  = threadIdx.x;
    const int lane = tid & 31;
    const int wid  = tid >> 5;
    const int wm   = wid & 3;          // M quarter (32 rows)
    const int wn   = wid >> 2;         // N half (64 cols)

    const int o0 = blockIdx.x * 128;
    const int mt = blockIdx.y;
    const int n  = mt >> 5;
    const int h0 = (mt & 31) * 2;

    // ldmatrix lane mappings
    const int a_row  = wm * 32 + (lane & 15);            // + mi*16
    const int a_kh   = lane >> 4;                        // 16B half within k16
    const int bg     = lane >> 3;
    const int b_row0 = wn * 64 + ((bg >> 1) << 3) + (lane & 7);  // + nb*16
    const int b_kh   = bg & 1;

    float acc[2][8][4];
#pragma unroll
    for (int mi = 0; mi < 2; ++mi)
#pragma unroll
        for (int ni = 0; ni < 8; ++ni)
#pragma unroll
            for (int q = 0; q < 4; ++q) acc[mi][ni][q] = 0.f;

    load_chunk(smbase, 0, n, h0, o0, tid);
    CP_COMMIT();

    for (int i = 0; i < NCHUNK; ++i) {
        CP_WAIT0();              // chunk i resident (this thread's copies)
        __syncthreads();         // all copies visible; all warps done with i-1
        if (i + 1 < NCHUNK) {    // prefetch i+1 into the buffer i-1 used
            load_chunk(smbase + ((i + 1) & 1) * STAGE_BYTES, i + 1, n, h0, o0, tid);
            CP_COMMIT();
        }

        const uint32_t sb = smbase + (i & 1) * STAGE_BYTES;
#pragma unroll
        for (int k16 = 0; k16 < 4; ++k16) {
            const int cha = 2 * k16 + a_kh;
            const int chb = 2 * k16 + b_kh;
            uint32_t ah[2][4], al[2][4], bb[4][4];
#pragma unroll
            for (int mi = 0; mi < 2; ++mi)
                LDSM4(ah[mi], sb + SWZ128(a_row + mi * 16, cha));
#pragma unroll
            for (int nb = 0; nb < 4; ++nb)
                LDSM4(bb[nb], sb + OFF_B + SWZ128(b_row0 + nb * 16, chb));
            // hi(A) x w
#pragma unroll
            for (int mi = 0; mi < 2; ++mi)
#pragma unroll
                for (int nb = 0; nb < 4; ++nb) {
                    MMA2(acc[mi][2*nb],   ah[mi], bb[nb][0], bb[nb][1]);
                    MMA2(acc[mi][2*nb+1], ah[mi], bb[nb][2], bb[nb][3]);
                }
            // lo(A) x w
#pragma unroll
            for (int mi = 0; mi < 2; ++mi)
                LDSM4(al[mi], sb + OFF_AL + SWZ128(a_row + mi * 16, cha));
#pragma unroll
            for (int mi = 0; mi < 2; ++mi)
#pragma unroll
                for (int nb = 0; nb < 4; ++nb) {
                    MMA2(acc[mi][2*nb],   al[mi], bb[nb][0], bb[nb][1]);
                    MMA2(acc[mi][2*nb+1], al[mi], bb[nb][2], bb[nb][3]);
                }
        }
    }

    // ---- epilogue: demod, noise, bias, leaky_relu * sqrt(2)
    const float nstrv = *nstr;
#pragma unroll
    for (int mi = 0; mi < 2; ++mi) {
#pragma unroll
        for (int half = 0; half < 2; ++half) {
            int m = wm * 32 + mi * 16 + (lane >> 2) + half * 8;
            int h = h0 + (m >> 6);
            int w = m & 63;
            float nz = noise[(n * HH + h) * WW + w] * nstrv;
            size_t base = ((size_t)((n * HH + h) * WW + w)) * OO + o0;
#pragma unroll
            for (int ni = 0; ni < 8; ++ni) {
                int oc = wn * 64 + ni * 8 + 2 * (lane & 3);
                float dm0 = g_dmul[n * OO + o0 + oc];
                float dm1 = g_dmul[n * OO + o0 + oc + 1];
                float b0 = bias[o0 + oc], b1 = bias[o0 + oc + 1];
                float y0 = fmaf(acc[mi][ni][half * 2],     dm0, nz + b0);
                float y1 = fmaf(acc[mi][ni][half * 2 + 1], dm1, nz + b1);
                y0 = (y0 > 0.f ? y0 : 0.2f * y0) * 1.4142135623730951f;
                y1 = (y1 > 0.f ? y1 : 0.2f * y1) * 1.4142135623730951f;
                *(float2*)(out + base + oc) = make_float2(y0, y1);
            }
        }
    }
}

// ---------------------------------------------------------------------------
extern "C" void kernel_launch(void* const* d_in, const int* in_sizes, int n_in,
                              void* d_out, int out_size)
{
    const float* x      = (const float*)d_in[0];
    const float* dlat   = (const float*)d_in[1];
    const float* sw     = (const float*)d_in[2];
    const float* sbv    = (const float*)d_in[3];
    const float* weight = (const float*)d_in[4];
    const float* bias   = (const float*)d_in[5];
    const float* nstr   = (const float*)d_in[6];
    const float* noise  = (const float*)d_in[7];
    const int*   lidx   = (const int*)  d_in[8];
    float* out = (float*)d_out;

    prep1_kernel<<<NN + CC, 512>>>(dlat, sw, sbv, lidx, weight);
    dmul_kernel<<<NN, 512>>>();
    prep3_kernel<<<32768 + 2304, 256>>>(x, weight);

    const int smem_bytes = 2 * STAGE_BYTES;   // 98304 per CTA (2 CTAs/SM)
    cudaFuncSetAttribute(conv_mma_kernel,
                         cudaFuncAttributeMaxDynamicSharedMemorySize, smem_bytes);
    conv_mma_kernel<<<dim3(4, 512), 256, smem_bytes>>>(bias, nstr, noise, out);
}

// round 7
// speedup vs baseline: 5.5692x; 1.6021x over previous
#include <cuda_runtime.h>
#include <cuda_fp16.h>
#include <stdint.h>

// ---------------------------------------------------------------------------
// StyleGAN2 modulated 3x3 conv, NHWC, N=16 H=W=64 C=O=512
// Round 7: SINGLE-product pure fp16 on mma.sync:  y = fp16(x*s) x fp16(w)
//          (calibrated error: w-round 2.07e-4 measured, +x-round -> ~2.9e-4)
//          CTA 128x128, warp 32x64, kc=64, 3-stage cp.async pipeline,
//          2 CTAs/SM. Tensor work halved vs round 6.
// ---------------------------------------------------------------------------

#define NN 16
#define HH 64
#define WW 64
#define CC 512
#define OO 512
#define NWD 14

#define STAGE_BYTES 32768   // A 16K | B 16K
#define OFF_B  16384
#define NCHUNK 72           // 9 taps x 8 c-chunks (kc=64)

// ---- device scratch (allocation-free) --------------------------------------
__device__ float g_s[NN * CC];
__device__ float g_dmul[NN * OO];
__device__ float g_ssq[CC * OO];
__device__ __half g_xh[NN * HH * WW * CC];   // fp16(x*s)
__device__ __half g_wt[9 * OO * CC];         // fp16 w^T [tap][o][c]

// ---- helpers -----------------------------------------------------------------
static __device__ __forceinline__ uint32_t smem_u32(const void* p) {
    uint32_t a;
    asm("{ .reg .u64 t; cvta.to.shared.u64 t, %1; cvt.u32.u64 %0, t; }"
        : "=r"(a) : "l"(p));
    return a;
}

#define CP16(dst, src, sz)                                                   \
    asm volatile("cp.async.cg.shared.global [%0], [%1], 16, %2;"             \
                 :: "r"(dst), "l"(src), "r"(sz) : "memory")
#define CP_COMMIT() asm volatile("cp.async.commit_group;" ::: "memory")
#define CP_WAIT1()  asm volatile("cp.async.wait_group 1;" ::: "memory")
#define CP_WAIT0()  asm volatile("cp.async.wait_group 0;" ::: "memory")

#define LDSM4(r, addr)                                                       \
    asm volatile("ldmatrix.sync.aligned.m8n8.x4.shared.b16 "                 \
                 "{%0,%1,%2,%3}, [%4];"                                      \
                 : "=r"((r)[0]), "=r"((r)[1]), "=r"((r)[2]), "=r"((r)[3])    \
                 : "r"(addr))

#define MMA2(d, a, b0, b1)                                                   \
    asm volatile("mma.sync.aligned.m16n8k16.row.col.f32.f16.f16.f32 "        \
                 "{%0,%1,%2,%3}, {%4,%5,%6,%7}, {%8,%9}, {%0,%1,%2,%3};"     \
                 : "+f"((d)[0]), "+f"((d)[1]), "+f"((d)[2]), "+f"((d)[3])    \
                 : "r"((a)[0]), "r"((a)[1]), "r"((a)[2]), "r"((a)[3]),       \
                   "r"(b0), "r"(b1))

// 128B rows, 8x16B chunks, XOR swizzle by row&7 (conflict-free ldmatrix)
#define SWZ128(row, ch) (((row) * 128) + ((((ch) ^ ((row) & 7))) << 4))

// ---- prep 1: style (blocks 0..15) + ssq (blocks 16..527) ----------------------
__global__ void prep1_kernel(const float* __restrict__ dlat,
                             const float* __restrict__ sw,
                             const float* __restrict__ sb,
                             const int*   __restrict__ lidx,
                             const float* __restrict__ weight)
{
    int bid = blockIdx.x;
    int t = threadIdx.x;
    if (bid < NN) {
        int n = bid;
        __shared__ float dl[CC];
        int li = *lidx;
        dl[t] = dlat[(n * NWD + li) * CC + t];
        __syncthreads();
        float acc = 0.f;
#pragma unroll 4
        for (int w = 0; w < CC; ++w)
            acc += dl[w] * sw[w * CC + t];
        g_s[n * CC + t] = acc * 0.044194173824159216f + sb[t];
    } else {
        int i = bid - NN;
        float acc = 0.f;
#pragma unroll
        for (int tp = 0; tp < 9; ++tp) {
            float v = weight[(tp * CC + i) * OO + t];
            acc += v * v;
        }
        g_ssq[i * OO + t] = acc;
    }
}

// ---- prep 2: dmul[n,o] ---------------------------------------------------------
__global__ void dmul_kernel()
{
    int n = blockIdx.x;
    int o = threadIdx.x;
    __shared__ float s2[CC];
    float sv = g_s[n * CC + o];
    s2[o] = sv * sv;
    __syncthreads();
    float acc = 0.f;
#pragma unroll 4
    for (int i = 0; i < CC; ++i)
        acc += s2[i] * g_ssq[i * OO + o];
    const float ws2 = 1.0f / 4608.0f;
    const float ws  = 0.014731391274719738f;
    g_dmul[n * OO + o] = ws * rsqrtf(ws2 * acc + 1e-8f);
}

// ---- prep 3: x*s -> fp16 (blocks < 32768) + w transpose fp16 (rest) -------------
__global__ void prep3_kernel(const float* __restrict__ x,
                             const float* __restrict__ weight)
{
    int bid = blockIdx.x;
    int tid = threadIdx.x;
    if (bid < 32768) {
        int t = bid * 256 + tid;
        int e = t * 4;
        int c = e & (CC - 1);
        int n = e >> 21;
        float4 v = *(const float4*)(x + e);
        float4 s = *(const float4*)(g_s + n * CC + c);
        __half h0 = __float2half_rn(v.x * s.x);
        __half h1 = __float2half_rn(v.y * s.y);
        __half h2 = __float2half_rn(v.z * s.z);
        __half h3 = __float2half_rn(v.w * s.w);
        uint2 ph;
        ph.x = (uint32_t)__half_as_ushort(h0) | ((uint32_t)__half_as_ushort(h1) << 16);
        ph.y = (uint32_t)__half_as_ushort(h2) | ((uint32_t)__half_as_ushort(h3) << 16);
        *(uint2*)(g_xh + e) = ph;
    } else {
        __shared__ float ts[32][33];
        int wb = bid - 32768;            // 0..2303
        int tap = wb >> 8;
        int rem = wb & 255;
        int o0 = (rem & 15) * 32;
        int c0 = (rem >> 4) * 32;
        int tx = tid & 31, ty = tid >> 5;
        for (int j = ty; j < 32; j += 8)
            ts[j][tx] = weight[(tap * CC + c0 + j) * OO + o0 + tx];
        __syncthreads();
        for (int j = ty; j < 32; j += 8) {
            float v = ts[tx][j];
            int oi = (tap * OO + o0 + j) * CC + c0 + tx;
            g_wt[oi] = __float2half_rn(v);
        }
    }
}

// ---- chunk staging via cp.async (256 threads, 8x16B each) -----------------------
static __device__ __forceinline__ void load_chunk(uint32_t sb, int ci,
                                                  int n, int h0, int o0, int tid)
{
    const int tap = ci >> 3;              // 0..8
    const int c0  = (ci & 7) * 64;        // kc=64
    const int dy  = tap / 3 - 1;
    const int dx  = tap % 3 - 1;
    const int r   = tid >> 1;             // 0..127
    const int cb  = (tid & 1) * 4;        // 4 consecutive 16B chunks
    const int r7  = r & 7;

    // ---- A rows (128 spatial, tap-shifted, zero-filled halo)
    int hs = h0 + (r >> 6) + dy;
    int ws = (r & 63) + dx;
    const bool ok = ((unsigned)hs < (unsigned)HH) && ((unsigned)ws < (unsigned)WW);
    const unsigned szA = ok ? 16u : 0u;
    const int hc = ok ? hs : 0;
    const int wc = ok ? ws : 0;
    const size_t aidx = ((size_t)((n * HH + hc) * WW + wc) * CC + c0 + cb * 8) * 2;
    const char* srcA = (const char*)g_xh + aidx;
#pragma unroll
    for (int c = 0; c < 4; ++c) {
        uint32_t d = sb + r * 128 + (((cb + c) ^ r7) << 4);
        CP16(d, srcA + c * 16, szA);
    }

    // ---- B rows (128 o-channels)
    const size_t bidx = ((size_t)((tap * OO + o0 + r) * CC) + c0 + cb * 8) * 2;
    const char* srcB = (const char*)g_wt + bidx;
#pragma unroll
    for (int c = 0; c < 4; ++c) {
        uint32_t d = sb + OFF_B + r * 128 + (((cb + c) ^ r7) << 4);
        CP16(d, srcB + c * 16, 16u);
    }
}

// ---- kernel 4: main conv on mma.sync ---------------------------------------------
__global__ __launch_bounds__(256, 2)
void conv_mma_kernel(const float* __restrict__ bias,
                     const float* __restrict__ nstr,
                     const float* __restrict__ noise,
                     float* __restrict__ out)
{
    extern __shared__ char dynsmem[];
    const uint32_t smbase = smem_u32(dynsmem);

    const int tid  = threadIdx.x;
    const int lane = tid & 31;
    const int wid  = tid >> 5;
    const int wm   = wid & 3;          // M quarter (32 rows)
    const int wn   = wid >> 2;         // N half (64 cols)

    const int o0 = blockIdx.x * 128;
    const int mt = blockIdx.y;
    const int n  = mt >> 5;
    const int h0 = (mt & 31) * 2;

    // ldmatrix lane mappings
    const int a_row  = wm * 32 + (lane & 15);            // + mi*16
    const int a_kh   = lane >> 4;
    const int bg     = lane >> 3;
    const int b_row0 = wn * 64 + ((bg >> 1) << 3) + (lane & 7);  // + nb*16
    const int b_kh   = bg & 1;

    float acc[2][8][4];
#pragma unroll
    for (int mi = 0; mi < 2; ++mi)
#pragma unroll
        for (int ni = 0; ni < 8; ++ni)
#pragma unroll
            for (int q = 0; q < 4; ++q) acc[mi][ni][q] = 0.f;

    // 3-stage pipeline prologue: chunks 0 and 1 in flight
    load_chunk(smbase, 0, n, h0, o0, tid); CP_COMMIT();
    load_chunk(smbase + STAGE_BYTES, 1, n, h0, o0, tid); CP_COMMIT();

    int s_cur = 0;                        // stage of chunk i
    for (int i = 0; i < NCHUNK; ++i) {
        if (i + 1 < NCHUNK) CP_WAIT1(); else CP_WAIT0();  // chunk i resident
        __syncthreads();                  // visible to all; all done with i-1
        if (i + 2 < NCHUNK) {             // prefetch i+2 into stage compute(i-1) used
            int s_nxt = s_cur + 2; if (s_nxt >= 3) s_nxt -= 3;
            load_chunk(smbase + s_nxt * STAGE_BYTES, i + 2, n, h0, o0, tid);
            CP_COMMIT();
        }

        const uint32_t sb = smbase + s_cur * STAGE_BYTES;
#pragma unroll
        for (int k16 = 0; k16 < 4; ++k16) {
            const int cha = 2 * k16 + a_kh;
            const int chb = 2 * k16 + b_kh;
            uint32_t aa[2][4], bb[4][4];
#pragma unroll
            for (int mi = 0; mi < 2; ++mi)
                LDSM4(aa[mi], sb + SWZ128(a_row + mi * 16, cha));
#pragma unroll
            for (int nb = 0; nb < 4; ++nb)
                LDSM4(bb[nb], sb + OFF_B + SWZ128(b_row0 + nb * 16, chb));
#pragma unroll
            for (int mi = 0; mi < 2; ++mi)
#pragma unroll
                for (int nb = 0; nb < 4; ++nb) {
                    MMA2(acc[mi][2*nb],   aa[mi], bb[nb][0], bb[nb][1]);
                    MMA2(acc[mi][2*nb+1], aa[mi], bb[nb][2], bb[nb][3]);
                }
        }
        ++s_cur; if (s_cur >= 3) s_cur = 0;
    }

    // ---- epilogue: demod, noise, bias, leaky_relu * sqrt(2)
    const float nstrv = *nstr;
#pragma unroll
    for (int mi = 0; mi < 2; ++mi) {
#pragma unroll
        for (int half = 0; half < 2; ++half) {
            int m = wm * 32 + mi * 16 + (lane >> 2) + half * 8;
            int h = h0 + (m >> 6);
            int w = m & 63;
            float nz = noise[(n * HH + h) * WW + w] * nstrv;
            size_t base = ((size_t)((n * HH + h) * WW + w)) * OO + o0;
#pragma unroll
            for (int ni = 0; ni < 8; ++ni) {
                int oc = wn * 64 + ni * 8 + 2 * (lane & 3);
                float dm0 = g_dmul[n * OO + o0 + oc];
                float dm1 = g_dmul[n * OO + o0 + oc + 1];
                float b0 = bias[o0 + oc], b1 = bias[o0 + oc + 1];
                float y0 = fmaf(acc[mi][ni][half * 2],     dm0, nz + b0);
                float y1 = fmaf(acc[mi][ni][half * 2 + 1], dm1, nz + b1);
                y0 = (y0 > 0.f ? y0 : 0.2f * y0) * 1.4142135623730951f;
                y1 = (y1 > 0.f ? y1 : 0.2f * y1) * 1.4142135623730951f;
                *(float2*)(out + base + oc) = make_float2(y0, y1);
            }
        }
    }
}

// ---------------------------------------------------------------------------
extern "C" void kernel_launch(void* const* d_in, const int* in_sizes, int n_in,
                              void* d_out, int out_size)
{
    const float* x      = (const float*)d_in[0];
    const float* dlat   = (const float*)d_in[1];
    const float* sw     = (const float*)d_in[2];
    const float* sbv    = (const float*)d_in[3];
    const float* weight = (const float*)d_in[4];
    const float* bias   = (const float*)d_in[5];
    const float* nstr   = (const float*)d_in[6];
    const float* noise  = (const float*)d_in[7];
    const int*   lidx   = (const int*)  d_in[8];
    float* out = (float*)d_out;

    prep1_kernel<<<NN + CC, 512>>>(dlat, sw, sbv, lidx, weight);
    dmul_kernel<<<NN, 512>>>();
    prep3_kernel<<<32768 + 2304, 256>>>(x, weight);

    const int smem_bytes = 3 * STAGE_BYTES;   // 98304 per CTA (2 CTAs/SM)
    cudaFuncSetAttribute(conv_mma_kernel,
                         cudaFuncAttributeMaxDynamicSharedMemorySize, smem_bytes);
    conv_mma_kernel<<<dim3(4, 512), 256, smem_bytes>>>(bias, nstr, noise, out);
}